// round 12
// baseline (speedup 1.0000x reference)
#include <cuda_runtime.h>
#include <cuda_fp16.h>
#include <math.h>
#include <stdint.h>

#define NB   2048
#define VD   30000
#define VDP  30080
#define E1D  1024
#define E2D  1024
#define CD   64
#define TD   512
#define EMBD 300
#define EMBP 320
#define BN_EPS 1e-5f

#define PHI_SC  256.f
#define BETA_SC 1024.f

#define OFF_Z      0
#define OFF_RECON  (NB*CD)
#define OFF_ZX     (OFF_RECON + (size_t)NB*VD)
#define OFF_ZC     (OFF_ZX + NB*CD)
#define OFF_PHI    (OFF_ZC + TD*CD)

// ---------------- scratch ----------------
__device__ __align__(1024) __half g_in_hi [(size_t)NB * VDP];
__device__ __align__(1024) __half g_in_lo [(size_t)NB * VDP];
__device__ __align__(1024) __half g_w1_hi [(size_t)E1D * VDP];
__device__ __align__(1024) __half g_w1_lo [(size_t)E1D * VDP];
__device__ __align__(1024) __half g_w2_hi [E2D * E1D];
__device__ __align__(1024) __half g_w2_lo [E2D * E1D];
__device__ __align__(1024) __half g_wmv_hi[2 * CD * E2D];
__device__ __align__(1024) __half g_wmv_lo[2 * CD * E2D];
__device__ float g_bmv[2 * CD];
__device__ __align__(1024) __half g_en1_hi[NB * E1D];
__device__ __align__(1024) __half g_en1_lo[NB * E1D];
__device__ __align__(1024) __half g_en2_hi[NB * E2D];
__device__ __align__(1024) __half g_en2_lo[NB * E2D];
__device__ __align__(1024) float g_part[2 * NB * E1D];
__device__ float g_pmv [NB * 2 * CD];
__device__ float g_stats[4 * CD];
__device__ float g_z[NB * CD];
__device__ float g_csq[TD];
__device__ float g_sinv[TD];
__device__ __align__(1024) __half g_phi [NB * TD];
__device__ __align__(1024) __half g_muz [TD * EMBP];
__device__ __align__(1024) __half g_emb [(size_t)VDP * EMBP];
__device__ float g_beta[(size_t)TD * VD];
__device__ __align__(1024) __half g_btT [(size_t)VDP * TD];

// ---------------- helpers ----------------
__device__ __forceinline__ uint32_t smem_to_u32(const void* p) {
    uint32_t a;
    asm("{ .reg .u64 t; cvta.to.shared.u64 t, %1; cvt.u32.u64 %0, t; }" : "=r"(a) : "l"(p));
    return a;
}
#define SWZ(x) ((uint32_t)(x) ^ ((((uint32_t)(x)) >> 3) & 0x70))

#define LDSM4(r, addr) \
    asm volatile("ldmatrix.sync.aligned.m8n8.x4.shared.b16 {%0,%1,%2,%3}, [%4];" \
        : "=r"((r)[0]), "=r"((r)[1]), "=r"((r)[2]), "=r"((r)[3]) : "r"(addr))

#define MMA16816(d, a, b0, b1) \
    asm volatile("mma.sync.aligned.m16n8k16.row.col.f32.f16.f16.f32 " \
        "{%0,%1,%2,%3}, {%4,%5,%6,%7}, {%8,%9}, {%0,%1,%2,%3};" \
        : "+f"((d)[0]), "+f"((d)[1]), "+f"((d)[2]), "+f"((d)[3]) \
        : "r"((a)[0]), "r"((a)[1]), "r"((a)[2]), "r"((a)[3]), "r"(b0), "r"(b1))

__device__ __forceinline__ float softplusf(float x) {
    return fmaxf(x, 0.f) + log1pf(expf(-fabsf(x)));
}
__device__ __forceinline__ void split2(float x, __half& h, __half& l) {
    h = __float2half_rn(x);
    l = __float2half_rn(x - __half2float(h));
}
__device__ __forceinline__ float block_reduce(float v, float* red, int op) {
    int t = threadIdx.x, w = t >> 5, l = t & 31, nw = blockDim.x >> 5;
    #pragma unroll
    for (int o = 16; o > 0; o >>= 1) {
        float u = __shfl_xor_sync(0xffffffffu, v, o);
        v = op ? fmaxf(v, u) : (v + u);
    }
    if (l == 0) red[w] = v;
    __syncthreads();
    if (t == 0) {
        float r = red[0];
        for (int i = 1; i < nw; i++) r = op ? fmaxf(r, red[i]) : (r + red[i]);
        red[32] = r;
    }
    __syncthreads();
    float r = red[32];
    __syncthreads();
    return r;
}

// ---------------- fp16 mma.sync GEMM ----------------
// CTA 128x128xBK64, 128 threads = 4 warps as 2(M)x2(N), warp tile 64x64.
// Fatter warp tiles cut LDSM bytes/MMA from 128 to 85 (smem-BW bound fix).
template<bool SPLIT, int OUTM, bool HAS_BIAS, int ACT, bool NPRED, int STAGES>
__global__ void __launch_bounds__(128, 1)
gemm_mma(const __half* __restrict__ Ah, const __half* __restrict__ Al,
         const __half* __restrict__ Bh, const __half* __restrict__ Bl,
         int Nn, int ldA, int ldB, int ldC, int kChunks,
         const float* __restrict__ bias, float* __restrict__ C,
         __half* __restrict__ Chi, __half* __restrict__ Clo, size_t zStride, float outScale)
{
    constexpr int NT = SPLIT ? 4 : 2;
    constexpr int TB = 16384;
    extern __shared__ char smem[];
    const uint32_t sb = smem_to_u32(smem);
    const int tid = threadIdx.x, lane = tid & 31, wid = tid >> 5;
    const int wM = wid & 1, wN = wid >> 1;
    const int m0 = blockIdx.y * 128, n0 = blockIdx.x * 128;
    const int per = kChunks / gridDim.z, cbeg = blockIdx.z * per;

    float acc[4][8][4];
    #pragma unroll
    for (int a = 0; a < 4; a++)
        #pragma unroll
        for (int b = 0; b < 8; b++)
            #pragma unroll
            for (int c = 0; c < 4; c++) acc[a][b][c] = 0.f;

    const __half* gp[4] = { Ah, SPLIT ? Al : Bh, Bh, Bl };
    const int rb4[4] = { m0, SPLIT ? m0 : n0, n0, n0 };
    const int ld4[4] = { ldA, SPLIT ? ldA : ldB, ldB, ldB };

    auto load_stage = [&](int s, int c) {
        const int k0 = c * 64;
        const uint32_t st = sb + s * (NT * TB);
        #pragma unroll
        for (int t = 0; t < NT; t++) {
            #pragma unroll
            for (int i = 0; i < 8; i++) {
                int lin = tid + i * 128, row = lin >> 3, kc = lin & 7;
                const __half* src = gp[t] + (size_t)(rb4[t] + row) * ld4[t] + k0 + kc * 8;
                uint32_t dst = st + t * TB + SWZ(row * 128 + kc * 16);
                asm volatile("cp.async.cg.shared.global [%0], [%1], 16;" :: "r"(dst), "l"(src));
            }
        }
        asm volatile("cp.async.commit_group;" ::: "memory");
    };

    auto compute_stage = [&](int s) {
        const uint32_t st = sb + s * (NT * TB);
        const uint32_t aH = st, aL = st + TB;
        const uint32_t bH = st + (SPLIT ? 2 : 1) * TB, bL = st + 3 * TB;
        #pragma unroll
        for (int ks = 0; ks < 4; ks++) {
            uint32_t rah[4][4], ral[4][4];
            #pragma unroll
            for (int mt = 0; mt < 4; mt++) {
                int row = wM * 64 + mt * 16 + (lane & 15);
                int kb  = ks * 32 + ((lane >> 4) << 4);
                uint32_t off = SWZ(row * 128 + kb);
                LDSM4(rah[mt], aH + off);
                if (SPLIT) LDSM4(ral[mt], aL + off);
            }
            #pragma unroll
            for (int p = 0; p < 4; p++) {
                uint32_t rbh[4], rbl[4];
                {
                    int nr = wN * 64 + p * 16 + (lane & 7) + ((lane >> 4) << 3);
                    int kb = ks * 32 + (((lane >> 3) & 1) << 4);
                    uint32_t off = SWZ(nr * 128 + kb);
                    LDSM4(rbh, bH + off);
                    if (SPLIT) LDSM4(rbl, bL + off);
                }
                // hh for all 8 accs of this p, then hl, then lh (indep distance 8)
                #pragma unroll
                for (int mt = 0; mt < 4; mt++) {
                    MMA16816(acc[mt][p * 2 + 0], rah[mt], rbh[0], rbh[1]);
                    MMA16816(acc[mt][p * 2 + 1], rah[mt], rbh[2], rbh[3]);
                }
                if (SPLIT) {
                    #pragma unroll
                    for (int mt = 0; mt < 4; mt++) {
                        MMA16816(acc[mt][p * 2 + 0], rah[mt], rbl[0], rbl[1]);
                        MMA16816(acc[mt][p * 2 + 1], rah[mt], rbl[2], rbl[3]);
                    }
                    #pragma unroll
                    for (int mt = 0; mt < 4; mt++) {
                        MMA16816(acc[mt][p * 2 + 0], ral[mt], rbh[0], rbh[1]);
                        MMA16816(acc[mt][p * 2 + 1], ral[mt], rbh[2], rbh[3]);
                    }
                }
            }
        }
    };

    #pragma unroll
    for (int s = 0; s < STAGES - 1; s++) load_stage(s, cbeg + s);
    for (int c = 0; c < per; c++) {
        if (c + STAGES - 1 < per) load_stage((c + STAGES - 1) % STAGES, cbeg + c + STAGES - 1);
        else asm volatile("cp.async.commit_group;" ::: "memory");
        asm volatile("cp.async.wait_group %0;" :: "n"(STAGES - 1));
        __syncthreads();
        compute_stage(c % STAGES);
        __syncthreads();
    }

    float* Cz = C;
    if (OUTM == 0) Cz = C + (size_t)blockIdx.z * zStride;
    #pragma unroll
    for (int mt = 0; mt < 4; mt++) {
        #pragma unroll
        for (int nt = 0; nt < 8; nt++) {
            int row = m0 + wM * 64 + mt * 16 + (lane >> 2);
            int col = n0 + wN * 64 + nt * 8 + ((lane & 3) << 1);
            if (NPRED && col >= Nn) continue;
            #pragma unroll
            for (int h = 0; h < 2; h++) {
                int r = row + h * 8;
                float v0 = acc[mt][nt][h * 2 + 0], v1 = acc[mt][nt][h * 2 + 1];
                if (OUTM == 0) { v0 *= outScale; v1 *= outScale; }
                if (HAS_BIAS) { v0 += bias[col]; v1 += bias[col + 1]; }
                if (ACT == 1) { v0 = softplusf(v0); v1 = softplusf(v1); }
                if (OUTM == 0) {
                    float2 f; f.x = v0; f.y = v1;
                    *reinterpret_cast<float2*>(Cz + (size_t)r * ldC + col) = f;
                } else {
                    __half h0, l0, h1, l1;
                    split2(v0, h0, l0); split2(v1, h1, l1);
                    __half2 ph; ph.x = h0; ph.y = h1;
                    __half2 pl; pl.x = l0; pl.y = l1;
                    *reinterpret_cast<__half2*>(Chi + (size_t)r * ldC + col) = ph;
                    *reinterpret_cast<__half2*>(Clo + (size_t)r * ldC + col) = pl;
                }
            }
        }
    }
}

// ---------------- conversion kernels ----------------
struct H4 { __half2 a, b; };
__device__ __forceinline__ void store_h4(__half* p, __half2 x, __half2 y) {
    H4 v; v.a = x; v.b = y;
    *reinterpret_cast<H4*>(p) = v;
}
__global__ void k_split_pad4(const float* __restrict__ s, __half* __restrict__ h,
                             __half* __restrict__ l, int rows, int sc, int dc) {
    size_t n4 = (size_t)rows * dc / 4;
    size_t i = (size_t)blockIdx.x * blockDim.x + threadIdx.x, st = (size_t)gridDim.x * blockDim.x;
    for (; i < n4; i += st) {
        size_t e = i * 4;
        int r = (int)(e / dc), c = (int)(e % dc);
        float4 v = make_float4(0.f, 0.f, 0.f, 0.f);
        if (c < sc) v = *reinterpret_cast<const float4*>(s + (size_t)r * sc + c);
        __half h0, l0, h1, l1, h2, l2, h3, l3;
        split2(v.x, h0, l0); split2(v.y, h1, l1); split2(v.z, h2, l2); split2(v.w, h3, l3);
        __half2 ph0; ph0.x = h0; ph0.y = h1;  __half2 ph1; ph1.x = h2; ph1.y = h3;
        __half2 pl0; pl0.x = l0; pl0.y = l1;  __half2 pl1; pl1.x = l2; pl1.y = l3;
        store_h4(h + e, ph0, ph1);
        store_h4(l + e, pl0, pl1);
    }
}
__global__ void k_conv_pad4(const float* __restrict__ s, __half* __restrict__ d,
                            int rows, int sc, int dc, float sc_mul) {
    size_t n4 = (size_t)rows * dc / 4;
    size_t i = (size_t)blockIdx.x * blockDim.x + threadIdx.x, st = (size_t)gridDim.x * blockDim.x;
    for (; i < n4; i += st) {
        size_t e = i * 4;
        int r = (int)(e / dc), c = (int)(e % dc);
        float4 v = make_float4(0.f, 0.f, 0.f, 0.f);
        if (c < sc) v = *reinterpret_cast<const float4*>(s + (size_t)r * sc + c);
        __half2 p0 = __floats2half2_rn(v.x * sc_mul, v.y * sc_mul);
        __half2 p1 = __floats2half2_rn(v.z * sc_mul, v.w * sc_mul);
        store_h4(d + e, p0, p1);
    }
}
__global__ void k_pack_wmv(const float* __restrict__ Wm, const float* __restrict__ bm,
                           const float* __restrict__ Wv, const float* __restrict__ bv) {
    int i = blockIdx.x * blockDim.x + threadIdx.x;
    const int tot = CD * E2D;
    if (i < tot) {
        __half h, l;
        split2(Wm[i], h, l); g_wmv_hi[i] = h;       g_wmv_lo[i] = l;
        split2(Wv[i], h, l); g_wmv_hi[tot + i] = h; g_wmv_lo[tot + i] = l;
    }
    if (i < CD) { g_bmv[i] = bm[i]; g_bmv[CD + i] = bv[i]; }
}
__global__ void k_reduce_en1(const float* __restrict__ b1) {
    int i = blockIdx.x * blockDim.x + threadIdx.x;
    if (i >= NB * E1D) return;
    float v = softplusf(g_part[i] + g_part[NB * E1D + i] + b1[i & (E1D - 1)]);
    __half h, l; split2(v, h, l);
    g_en1_hi[i] = h; g_en1_lo[i] = l;
}
__global__ void k_pmv_reduce() {
    int i = blockIdx.x * blockDim.x + threadIdx.x;
    if (i >= NB * 2 * CD) return;
    float v = g_bmv[i & (2 * CD - 1)];
    #pragma unroll
    for (int z = 0; z < 4; z++) v += g_part[z * NB * 2 * CD + i];
    g_pmv[i] = v;
}
__global__ void k_bn_stats() {
    int c = blockIdx.x;
    float s = 0.f, s2 = 0.f;
    for (int n = threadIdx.x; n < NB; n += blockDim.x) {
        float x = g_pmv[n * (2 * CD) + c];
        s += x; s2 += x * x;
    }
    __shared__ float red[33];
    float S = block_reduce(s, red, 0), S2 = block_reduce(s2, red, 0);
    if (threadIdx.x == 0) {
        float mean = S * (1.f / NB);
        float var  = S2 * (1.f / NB) - mean * mean;
        g_stats[c] = mean;
        g_stats[2 * CD + c] = rsqrtf(var + BN_EPS);
    }
}
__global__ void k_z(const float* __restrict__ eps, const float* __restrict__ gm,
                    const float* __restrict__ betam, const float* __restrict__ gv,
                    const float* __restrict__ betav, float* __restrict__ oz, float* __restrict__ ozx) {
    int i = blockIdx.x * blockDim.x + threadIdx.x;
    if (i >= NB * CD) return;
    int n = i / CD, c = i % CD;
    float pm = g_pmv[n * (2 * CD) + c], pv = g_pmv[n * (2 * CD) + CD + c];
    float pmean   = (pm - g_stats[c])      * g_stats[2 * CD + c] * gm[c] + betam[c];
    float plogvar = (pv - g_stats[CD + c]) * g_stats[3 * CD + c] * gv[c] + betav[c];
    float z = pmean + expf(0.5f * plogvar) * eps[i];
    g_z[i] = z; oz[i] = z; ozx[i] = z;
}
__global__ void k_centres(const float* __restrict__ cen, float* __restrict__ ozc) {
    int t = blockIdx.x, l = threadIdx.x;
    float a = cen[t * CD + l], b = cen[t * CD + 32 + l];
    ozc[t * CD + l] = a; ozc[t * CD + 32 + l] = b;
    float s = a * a + b * b;
    #pragma unroll
    for (int o = 16; o > 0; o >>= 1) s += __shfl_xor_sync(0xffffffffu, s, o);
    if (l == 0) g_csq[t] = s;
}
__global__ void k_rbf(const float* __restrict__ cen, float* __restrict__ ophi) {
    int n = blockIdx.x, t = threadIdx.x;
    __shared__ float zsh[CD];
    __shared__ float red[33];
    if (t < CD) zsh[t] = g_z[n * CD + t];
    __syncthreads();
    float dot = 0.f, zsq = 0.f;
    const float* cp = cen + t * CD;
    #pragma unroll
    for (int k = 0; k < CD; k++) {
        float zk = zsh[k];
        dot = fmaf(zk, cp[k], dot);
        zsq = fmaf(zk, zk, zsq);
    }
    float logit = -0.5f * (zsq + g_csq[t] - 2.f * dot);
    float bm = block_reduce(logit, red, 1);
    float e  = expf(logit - bm);
    float bs = block_reduce(e, red, 0);
    float p  = e / bs;
    ophi[(size_t)n * TD + t] = p;
    g_phi[n * TD + t] = __float2half_rn(p * PHI_SC);
}
__global__ void k_softmax_V() {
    int row = blockIdx.x;
    float* X = g_beta + (size_t)row * VD;
    __shared__ float red[33];
    int t = threadIdx.x;
    float s = 0.f;
    for (int i = t; i < VD; i += blockDim.x) { float e = expf(X[i]); X[i] = e; s += e; }
    float bs = block_reduce(s, red, 0);
    if (t == 0) g_sinv[row] = 1.f / bs;
}
__global__ void k_transpose() {
    __shared__ float tile[32][33];
    int v0 = blockIdx.x * 32, t0 = blockIdx.y * 32;
    int tx = threadIdx.x, ty = threadIdx.y;
    #pragma unroll
    for (int i = 0; i < 4; i++) {
        int vc = v0 + tx;
        tile[ty + i * 8][tx] = (vc < VD) ? g_beta[(size_t)(t0 + ty + i * 8) * VD + vc] : 0.f;
    }
    __syncthreads();
    float sc = g_sinv[t0 + tx] * BETA_SC;
    #pragma unroll
    for (int i = 0; i < 4; i++) {
        int vr = v0 + ty + i * 8, tc = t0 + tx;
        if (vr < VD) g_btT[(size_t)vr * TD + tc] = __float2half_rn(tile[tx][ty + i * 8] * sc);
    }
}

// ---------------- launch ----------------
extern "C" void kernel_launch(void* const* d_in, const int* in_sizes, int n_in,
                              void* d_out, int out_size) {
    const float* input_  = (const float*)d_in[0];
    const float* eps     = (const float*)d_in[2];
    const float* W1      = (const float*)d_in[3];
    const float* b1      = (const float*)d_in[4];
    const float* W2      = (const float*)d_in[5];
    const float* b2      = (const float*)d_in[6];
    const float* Wm      = (const float*)d_in[7];
    const float* bm      = (const float*)d_in[8];
    const float* Wv      = (const float*)d_in[9];
    const float* bv      = (const float*)d_in[10];
    const float* gm      = (const float*)d_in[11];
    const float* betam   = (const float*)d_in[12];
    const float* gv      = (const float*)d_in[13];
    const float* betav   = (const float*)d_in[14];
    const float* centres = (const float*)d_in[15];
    const float* mu_z    = (const float*)d_in[16];
    const float* emb     = (const float*)d_in[17];

    float* out       = (float*)d_out;
    float* out_z     = out + OFF_Z;
    float* out_recon = out + OFF_RECON;
    float* out_zx    = out + OFF_ZX;
    float* out_zc    = out + OFF_ZC;
    float* out_phi   = out + OFF_PHI;

    #define GSA(p, s) void* p; cudaGetSymbolAddress(&p, s)
    GSA(p_in_hi, g_in_hi);   GSA(p_in_lo, g_in_lo);
    GSA(p_w1_hi, g_w1_hi);   GSA(p_w1_lo, g_w1_lo);
    GSA(p_w2_hi, g_w2_hi);   GSA(p_w2_lo, g_w2_lo);
    GSA(p_wmv_hi, g_wmv_hi); GSA(p_wmv_lo, g_wmv_lo);
    GSA(p_part, g_part);
    GSA(p_en1_hi, g_en1_hi); GSA(p_en1_lo, g_en1_lo);
    GSA(p_en2_hi, g_en2_hi); GSA(p_en2_lo, g_en2_lo);
    GSA(p_phi, g_phi);       GSA(p_muz, g_muz);
    GSA(p_emb, g_emb);       GSA(p_beta, g_beta);
    GSA(p_btT, g_btT);

    static cudaStream_t s2 = nullptr;
    static cudaEvent_t e0 = nullptr, eW = nullptr, eB = nullptr;
    if (!s2) {
        cudaStreamCreateWithFlags(&s2, cudaStreamNonBlocking);
        cudaEventCreateWithFlags(&e0, cudaEventDisableTiming);
        cudaEventCreateWithFlags(&eW, cudaEventDisableTiming);
        cudaEventCreateWithFlags(&eB, cudaEventDisableTiming);
    }

    const int SM_SPLIT  = 3 * 4 * 16384;   // 196608
    const int SM_SINGLE = 3 * 2 * 16384;   //  98304
    cudaFuncSetAttribute((const void*)gemm_mma<true, 0, false, 0, false, 3>,
                         cudaFuncAttributeMaxDynamicSharedMemorySize, SM_SPLIT);
    cudaFuncSetAttribute((const void*)gemm_mma<true, 1, true, 1, false, 3>,
                         cudaFuncAttributeMaxDynamicSharedMemorySize, SM_SPLIT);
    cudaFuncSetAttribute((const void*)gemm_mma<false, 0, false, 0, true, 3>,
                         cudaFuncAttributeMaxDynamicSharedMemorySize, SM_SINGLE);

    // ---- critical path: GEMM1 prerequisites ----
    k_split_pad4<<<1024, 256>>>(input_, (__half*)p_in_hi, (__half*)p_in_lo, NB, VD, VDP);
    k_split_pad4<<<1024, 256>>>(W1, (__half*)p_w1_hi, (__half*)p_w1_lo, E1D, VD, VDP);

    // fork side stream
    cudaEventRecord(e0, 0);
    cudaStreamWaitEvent(s2, e0, 0);
    k_split_pad4<<<512, 256, 0, s2>>>(W2, (__half*)p_w2_hi, (__half*)p_w2_lo, E2D, E1D, E1D);

    // GEMM1: input @ W1^T (3-split, split-K=2)
    gemm_mma<true, 0, false, 0, false, 3><<<dim3(E1D / 128, NB / 128, 2), 128, SM_SPLIT>>>(
        (const __half*)p_in_hi, (const __half*)p_in_lo,
        (const __half*)p_w1_hi, (const __half*)p_w1_lo,
        E1D, VDP, VDP, E1D, VDP / 64, nullptr, (float*)p_part, nullptr, nullptr,
        (size_t)NB * E1D, 1.f);

    // side stream: GEMM2/pmv weights + centres, then beta chain
    k_pack_wmv<<<(CD * E2D + 255) / 256, 256, 0, s2>>>(Wm, bm, Wv, bv);
    k_centres<<<TD, 32, 0, s2>>>(centres, out_zc);
    cudaEventRecord(eW, s2);
    k_conv_pad4<<<128, 256, 0, s2>>>(mu_z, (__half*)p_muz, TD, EMBD, EMBP, 1.f);
    k_conv_pad4<<<512, 256, 0, s2>>>(emb, (__half*)p_emb, VD, EMBD, EMBP, 1.f);
    gemm_mma<false, 0, false, 0, true, 3><<<dim3(VDP / 128, TD / 128, 1), 128, SM_SINGLE, s2>>>(
        (const __half*)p_muz, nullptr, (const __half*)p_emb, nullptr,
        VD, EMBP, EMBP, VD, EMBP / 64, nullptr, (float*)p_beta, nullptr, nullptr, 0, 1.f);
    k_softmax_V<<<TD, 512, 0, s2>>>();
    k_transpose<<<dim3((VD + 31) / 32, TD / 32), dim3(32, 8), 0, s2>>>();
    cudaEventRecord(eB, s2);

    // main stream continues
    k_reduce_en1<<<(NB * E1D + 255) / 256, 256>>>(b1);

    cudaStreamWaitEvent(0, eW, 0);
    gemm_mma<true, 1, true, 1, false, 3><<<dim3(E2D / 128, NB / 128, 1), 128, SM_SPLIT>>>(
        (const __half*)p_en1_hi, (const __half*)p_en1_lo,
        (const __half*)p_w2_hi, (const __half*)p_w2_lo,
        E2D, E1D, E1D, E2D, E1D / 64, b2, nullptr,
        (__half*)p_en2_hi, (__half*)p_en2_lo, 0, 1.f);

    gemm_mma<true, 0, false, 0, false, 3><<<dim3(1, NB / 128, 4), 128, SM_SPLIT>>>(
        (const __half*)p_en2_hi, (const __half*)p_en2_lo,
        (const __half*)p_wmv_hi, (const __half*)p_wmv_lo,
        2 * CD, E2D, E2D, 2 * CD, E2D / 64, nullptr, (float*)p_part, nullptr, nullptr,
        (size_t)NB * 2 * CD, 1.f);
    k_pmv_reduce<<<(NB * 2 * CD + 255) / 256, 256>>>();

    k_bn_stats<<<2 * CD, 256>>>();
    k_z<<<(NB * CD + 255) / 256, 256>>>(eps, gm, betam, gv, betav, out_z, out_zx);
    k_rbf<<<NB, TD>>>(centres, out_phi);

    cudaStreamWaitEvent(0, eB, 0);
    gemm_mma<false, 0, false, 0, true, 3><<<dim3(VDP / 128, NB / 128, 1), 128, SM_SINGLE>>>(
        (const __half*)p_phi, nullptr, (const __half*)p_btT, nullptr,
        VD, TD, TD, VD, TD / 64, nullptr, out_recon, nullptr, nullptr, 0,
        1.f / (PHI_SC * BETA_SC));
}

// round 15
// speedup vs baseline: 1.5379x; 1.5379x over previous
#include <cuda_runtime.h>
#include <cuda_fp16.h>
#include <math.h>
#include <stdint.h>

#define NB   2048
#define VD   30000
#define VDP  30208            // mult of 256
#define E1D  1024
#define E2D  1024
#define CD   64
#define TD   512
#define EMBD 300
#define EMBP 320
#define BN_EPS 1e-5f

#define PHI_SC  256.f
#define BETA_SC 1024.f

#define OFF_Z      0
#define OFF_RECON  (NB*CD)
#define OFF_ZX     (OFF_RECON + (size_t)NB*VD)
#define OFF_ZC     (OFF_ZX + NB*CD)
#define OFF_PHI    (OFF_ZC + TD*CD)

// ---------------- scratch ----------------
__device__ __align__(1024) __half g_in_hi [(size_t)NB * VDP];
__device__ __align__(1024) __half g_in_lo [(size_t)NB * VDP];
__device__ __align__(1024) __half g_w1_hi [(size_t)E1D * VDP];
__device__ __align__(1024) __half g_w1_lo [(size_t)E1D * VDP];
__device__ __align__(1024) __half g_w2_hi [E2D * E1D];
__device__ __align__(1024) __half g_w2_lo [E2D * E1D];
__device__ __align__(1024) __half g_wmv_hi[256 * E2D];   // rows 128..255 stay zero
__device__ __align__(1024) __half g_wmv_lo[256 * E2D];
__device__ float g_bmv[2 * CD];
__device__ __align__(1024) __half g_en1_hi[NB * E1D];
__device__ __align__(1024) __half g_en1_lo[NB * E1D];
__device__ __align__(1024) __half g_en2_hi[NB * E2D];
__device__ __align__(1024) __half g_en2_lo[NB * E2D];
__device__ __align__(1024) float g_part[4 * NB * 2 * CD > 2 * NB * E1D ? 4 * NB * 2 * CD : 2 * NB * E1D];
__device__ float g_pmv [NB * 2 * CD];
__device__ float g_stats[4 * CD];
__device__ float g_z[NB * CD];
__device__ float g_csq[TD];
__device__ float g_sinv[TD];
__device__ __align__(1024) __half g_phi [NB * TD];
__device__ __align__(1024) __half g_muz [TD * EMBP];
__device__ __align__(1024) __half g_emb [(size_t)VDP * EMBP];
__device__ float g_beta[(size_t)TD * VD];
__device__ __align__(1024) __half g_btT [(size_t)VDP * TD];

// ---------------- helpers ----------------
__device__ __forceinline__ uint32_t smem_to_u32(const void* p) {
    uint32_t a;
    asm("{ .reg .u64 t; cvta.to.shared.u64 t, %1; cvt.u32.u64 %0, t; }" : "=r"(a) : "l"(p));
    return a;
}
#define SWZ(x) ((uint32_t)(x) ^ ((((uint32_t)(x)) >> 3) & 0x70))

#define LDSM4(r, addr) \
    asm volatile("ldmatrix.sync.aligned.m8n8.x4.shared.b16 {%0,%1,%2,%3}, [%4];" \
        : "=r"((r)[0]), "=r"((r)[1]), "=r"((r)[2]), "=r"((r)[3]) : "r"(addr))

#define MMA16816(d, a, b0, b1) \
    asm volatile("mma.sync.aligned.m16n8k16.row.col.f32.f16.f16.f32 " \
        "{%0,%1,%2,%3}, {%4,%5,%6,%7}, {%8,%9}, {%0,%1,%2,%3};" \
        : "+f"((d)[0]), "+f"((d)[1]), "+f"((d)[2]), "+f"((d)[3]) \
        : "r"((a)[0]), "r"((a)[1]), "r"((a)[2]), "r"((a)[3]), "r"(b0), "r"(b1))

__device__ __forceinline__ float softplusf(float x) {
    return fmaxf(x, 0.f) + log1pf(expf(-fabsf(x)));
}
__device__ __forceinline__ void split2(float x, __half& h, __half& l) {
    h = __float2half_rn(x);
    l = __float2half_rn(x - __half2float(h));
}
__device__ __forceinline__ float block_reduce(float v, float* red, int op) {
    int t = threadIdx.x, w = t >> 5, l = t & 31, nw = blockDim.x >> 5;
    #pragma unroll
    for (int o = 16; o > 0; o >>= 1) {
        float u = __shfl_xor_sync(0xffffffffu, v, o);
        v = op ? fmaxf(v, u) : (v + u);
    }
    if (l == 0) red[w] = v;
    __syncthreads();
    if (t == 0) {
        float r = red[0];
        for (int i = 1; i < nw; i++) r = op ? fmaxf(r, red[i]) : (r + red[i]);
        red[32] = r;
    }
    __syncthreads();
    float r = red[32];
    __syncthreads();
    return r;
}

// ---------------- fp16 mma.sync GEMM ----------------
// CTA tile 128(M) x 256(N) x 64(K). 256 threads = 8 warps as 2(M) x 4(N),
// warp tile 64x64 (85 B LDSM per MMA; 2 warps/SMSP for latency hiding).
template<bool SPLIT, int OUTM, bool HAS_BIAS, int ACT, bool NPRED, int STAGES>
__global__ void __launch_bounds__(256, 1)
gemm_mma(const __half* __restrict__ Ah, const __half* __restrict__ Al,
         const __half* __restrict__ Bh, const __half* __restrict__ Bl,
         int Nn, int ldA, int ldB, int ldC, int kChunks,
         const float* __restrict__ bias, float* __restrict__ C,
         __half* __restrict__ Chi, __half* __restrict__ Clo, size_t zStride, float outScale)
{
    constexpr int TA  = 128 * 128;               // A tile bytes
    constexpr int TBB = 256 * 128;               // B tile bytes
    constexpr int STG = (SPLIT ? 2 * TA + 2 * TBB : TA + TBB);
    extern __shared__ char smem[];
    const uint32_t sb = smem_to_u32(smem);
    const int tid = threadIdx.x, lane = tid & 31, wid = tid >> 5;
    const int wM = wid & 1, wN = wid >> 1;       // 2(M) x 4(N)
    const int m0 = blockIdx.y * 128, n0 = blockIdx.x * 256;
    const int per = kChunks / gridDim.z, cbeg = blockIdx.z * per;

    float acc[4][8][4];
    #pragma unroll
    for (int a = 0; a < 4; a++)
        #pragma unroll
        for (int b = 0; b < 8; b++)
            #pragma unroll
            for (int c = 0; c < 4; c++) acc[a][b][c] = 0.f;

    auto load_stage = [&](int s, int c) {
        const int k0 = c * 64;
        const uint32_t st = sb + s * STG;
        #pragma unroll
        for (int t = 0; t < (SPLIT ? 2 : 1); t++) {
            const __half* base = t ? Al : Ah;
            #pragma unroll
            for (int i = 0; i < 4; i++) {
                int lin = tid + i * 256, row = lin >> 3, kc = lin & 7;
                const __half* src = base + (size_t)(m0 + row) * ldA + k0 + kc * 8;
                uint32_t dst = st + t * TA + SWZ(row * 128 + kc * 16);
                asm volatile("cp.async.cg.shared.global [%0], [%1], 16;" :: "r"(dst), "l"(src));
            }
        }
        const uint32_t bo = st + (SPLIT ? 2 : 1) * TA;
        #pragma unroll
        for (int t = 0; t < (SPLIT ? 2 : 1); t++) {
            const __half* base = t ? Bl : Bh;
            #pragma unroll
            for (int i = 0; i < 8; i++) {
                int lin = tid + i * 256, row = lin >> 3, kc = lin & 7;
                const __half* src = base + (size_t)(n0 + row) * ldB + k0 + kc * 8;
                uint32_t dst = bo + t * TBB + SWZ(row * 128 + kc * 16);
                asm volatile("cp.async.cg.shared.global [%0], [%1], 16;" :: "r"(dst), "l"(src));
            }
        }
        asm volatile("cp.async.commit_group;" ::: "memory");
    };

    auto compute_stage = [&](int s) {
        const uint32_t st = sb + s * STG;
        const uint32_t aH = st, aL = st + TA;
        const uint32_t bH = st + (SPLIT ? 2 : 1) * TA, bL = bH + TBB;
        #pragma unroll
        for (int ks = 0; ks < 4; ks++) {
            uint32_t rah[4][4], ral[4][4];
            #pragma unroll
            for (int mt = 0; mt < 4; mt++) {
                int row = wM * 64 + mt * 16 + (lane & 15);
                int kb  = ks * 32 + ((lane >> 4) << 4);
                uint32_t off = SWZ(row * 128 + kb);
                LDSM4(rah[mt], aH + off);
                if (SPLIT) LDSM4(ral[mt], aL + off);
            }
            #pragma unroll
            for (int p = 0; p < 4; p++) {
                uint32_t rbh[4], rbl[4];
                {
                    int nr = wN * 64 + p * 16 + (lane & 7) + ((lane >> 4) << 3);
                    int kb = ks * 32 + (((lane >> 3) & 1) << 4);
                    uint32_t off = SWZ(nr * 128 + kb);
                    LDSM4(rbh, bH + off);
                    if (SPLIT) LDSM4(rbl, bL + off);
                }
                #pragma unroll
                for (int mt = 0; mt < 4; mt++) {
                    MMA16816(acc[mt][p * 2 + 0], rah[mt], rbh[0], rbh[1]);
                    MMA16816(acc[mt][p * 2 + 1], rah[mt], rbh[2], rbh[3]);
                }
                if (SPLIT) {
                    #pragma unroll
                    for (int mt = 0; mt < 4; mt++) {
                        MMA16816(acc[mt][p * 2 + 0], rah[mt], rbl[0], rbl[1]);
                        MMA16816(acc[mt][p * 2 + 1], rah[mt], rbl[2], rbl[3]);
                    }
                    #pragma unroll
                    for (int mt = 0; mt < 4; mt++) {
                        MMA16816(acc[mt][p * 2 + 0], ral[mt], rbh[0], rbh[1]);
                        MMA16816(acc[mt][p * 2 + 1], ral[mt], rbh[2], rbh[3]);
                    }
                }
            }
        }
    };

    #pragma unroll
    for (int s = 0; s < STAGES - 1; s++) load_stage(s, cbeg + s);
    for (int c = 0; c < per; c++) {
        if (c + STAGES - 1 < per) load_stage((c + STAGES - 1) % STAGES, cbeg + c + STAGES - 1);
        else asm volatile("cp.async.commit_group;" ::: "memory");
        asm volatile("cp.async.wait_group %0;" :: "n"(STAGES - 1));
        __syncthreads();
        compute_stage(c % STAGES);
        __syncthreads();
    }

    float* Cz = C;
    if (OUTM == 0) Cz = C + (size_t)blockIdx.z * zStride;
    #pragma unroll
    for (int mt = 0; mt < 4; mt++) {
        #pragma unroll
        for (int nt = 0; nt < 8; nt++) {
            int row = m0 + wM * 64 + mt * 16 + (lane >> 2);
            int col = n0 + wN * 64 + nt * 8 + ((lane & 3) << 1);
            if (NPRED && col >= Nn) continue;
            #pragma unroll
            for (int h = 0; h < 2; h++) {
                int r = row + h * 8;
                float v0 = acc[mt][nt][h * 2 + 0], v1 = acc[mt][nt][h * 2 + 1];
                if (OUTM == 0) { v0 *= outScale; v1 *= outScale; }
                if (HAS_BIAS) { v0 += bias[col]; v1 += bias[col + 1]; }
                if (ACT == 1) { v0 = softplusf(v0); v1 = softplusf(v1); }
                if (OUTM == 0) {
                    float2 f; f.x = v0; f.y = v1;
                    *reinterpret_cast<float2*>(Cz + (size_t)r * ldC + col) = f;
                } else {
                    __half h0, l0, h1, l1;
                    split2(v0, h0, l0); split2(v1, h1, l1);
                    __half2 ph; ph.x = h0; ph.y = h1;
                    __half2 pl; pl.x = l0; pl.y = l1;
                    *reinterpret_cast<__half2*>(Chi + (size_t)r * ldC + col) = ph;
                    *reinterpret_cast<__half2*>(Clo + (size_t)r * ldC + col) = pl;
                }
            }
        }
    }
}

// ---------------- conversion kernels ----------------
struct H4 { __half2 a, b; };
__device__ __forceinline__ void store_h4(__half* p, __half2 x, __half2 y) {
    H4 v; v.a = x; v.b = y;
    *reinterpret_cast<H4*>(p) = v;
}
__global__ void k_split_pad4(const float* __restrict__ s, __half* __restrict__ h,
                             __half* __restrict__ l, int rows, int sc, int dc) {
    size_t n4 = (size_t)rows * dc / 4;
    size_t i = (size_t)blockIdx.x * blockDim.x + threadIdx.x, st = (size_t)gridDim.x * blockDim.x;
    for (; i < n4; i += st) {
        size_t e = i * 4;
        int r = (int)(e / dc), c = (int)(e % dc);
        float4 v = make_float4(0.f, 0.f, 0.f, 0.f);
        if (c < sc) v = *reinterpret_cast<const float4*>(s + (size_t)r * sc + c);
        __half h0, l0, h1, l1, h2, l2, h3, l3;
        split2(v.x, h0, l0); split2(v.y, h1, l1); split2(v.z, h2, l2); split2(v.w, h3, l3);
        __half2 ph0; ph0.x = h0; ph0.y = h1;  __half2 ph1; ph1.x = h2; ph1.y = h3;
        __half2 pl0; pl0.x = l0; pl0.y = l1;  __half2 pl1; pl1.x = l2; pl1.y = l3;
        store_h4(h + e, ph0, ph1);
        store_h4(l + e, pl0, pl1);
    }
}
__global__ void k_conv_pad4(const float* __restrict__ s, __half* __restrict__ d,
                            int rows, int sc, int dc, float sc_mul) {
    size_t n4 = (size_t)rows * dc / 4;
    size_t i = (size_t)blockIdx.x * blockDim.x + threadIdx.x, st = (size_t)gridDim.x * blockDim.x;
    for (; i < n4; i += st) {
        size_t e = i * 4;
        int r = (int)(e / dc), c = (int)(e % dc);
        float4 v = make_float4(0.f, 0.f, 0.f, 0.f);
        if (c < sc) v = *reinterpret_cast<const float4*>(s + (size_t)r * sc + c);
        __half2 p0 = __floats2half2_rn(v.x * sc_mul, v.y * sc_mul);
        __half2 p1 = __floats2half2_rn(v.z * sc_mul, v.w * sc_mul);
        store_h4(d + e, p0, p1);
    }
}
__global__ void k_pack_wmv(const float* __restrict__ Wm, const float* __restrict__ bm,
                           const float* __restrict__ Wv, const float* __restrict__ bv) {
    int i = blockIdx.x * blockDim.x + threadIdx.x;
    const int tot = CD * E2D;
    if (i < tot) {
        __half h, l;
        split2(Wm[i], h, l); g_wmv_hi[i] = h;       g_wmv_lo[i] = l;
        split2(Wv[i], h, l); g_wmv_hi[tot + i] = h; g_wmv_lo[tot + i] = l;
    }
    if (i < CD) { g_bmv[i] = bm[i]; g_bmv[CD + i] = bv[i]; }
}
__global__ void k_reduce_en1(const float* __restrict__ b1) {
    int i = blockIdx.x * blockDim.x + threadIdx.x;
    if (i >= NB * E1D) return;
    float v = softplusf(g_part[i] + g_part[NB * E1D + i] + b1[i & (E1D - 1)]);
    __half h, l; split2(v, h, l);
    g_en1_hi[i] = h; g_en1_lo[i] = l;
}
__global__ void k_pmv_reduce() {
    int i = blockIdx.x * blockDim.x + threadIdx.x;
    if (i >= NB * 2 * CD) return;
    float v = g_bmv[i & (2 * CD - 1)];
    #pragma unroll
    for (int z = 0; z < 4; z++) v += g_part[(size_t)z * NB * 2 * CD + i];
    g_pmv[i] = v;
}
__global__ void k_bn_stats() {
    int c = blockIdx.x;
    float s = 0.f, s2 = 0.f;
    for (int n = threadIdx.x; n < NB; n += blockDim.x) {
        float x = g_pmv[n * (2 * CD) + c];
        s += x; s2 += x * x;
    }
    __shared__ float red[33];
    float S = block_reduce(s, red, 0), S2 = block_reduce(s2, red, 0);
    if (threadIdx.x == 0) {
        float mean = S * (1.f / NB);
        float var  = S2 * (1.f / NB) - mean * mean;
        g_stats[c] = mean;
        g_stats[2 * CD + c] = rsqrtf(var + BN_EPS);
    }
}
__global__ void k_z(const float* __restrict__ eps, const float* __restrict__ gm,
                    const float* __restrict__ betam, const float* __restrict__ gv,
                    const float* __restrict__ betav, float* __restrict__ oz, float* __restrict__ ozx) {
    int i = blockIdx.x * blockDim.x + threadIdx.x;
    if (i >= NB * CD) return;
    int n = i / CD, c = i % CD;
    float pm = g_pmv[n * (2 * CD) + c], pv = g_pmv[n * (2 * CD) + CD + c];
    float pmean   = (pm - g_stats[c])      * g_stats[2 * CD + c] * gm[c] + betam[c];
    float plogvar = (pv - g_stats[CD + c]) * g_stats[3 * CD + c] * gv[c] + betav[c];
    float z = pmean + expf(0.5f * plogvar) * eps[i];
    g_z[i] = z; oz[i] = z; ozx[i] = z;
}
__global__ void k_centres(const float* __restrict__ cen, float* __restrict__ ozc) {
    int t = blockIdx.x, l = threadIdx.x;
    float a = cen[t * CD + l], b = cen[t * CD + 32 + l];
    ozc[t * CD + l] = a; ozc[t * CD + 32 + l] = b;
    float s = a * a + b * b;
    #pragma unroll
    for (int o = 16; o > 0; o >>= 1) s += __shfl_xor_sync(0xffffffffu, s, o);
    if (l == 0) g_csq[t] = s;
}
__global__ void k_rbf(const float* __restrict__ cen, float* __restrict__ ophi) {
    int n = blockIdx.x, t = threadIdx.x;
    __shared__ float zsh[CD];
    __shared__ float red[33];
    if (t < CD) zsh[t] = g_z[n * CD + t];
    __syncthreads();
    float dot = 0.f, zsq = 0.f;
    const float* cp = cen + t * CD;
    #pragma unroll
    for (int k = 0; k < CD; k++) {
        float zk = zsh[k];
        dot = fmaf(zk, cp[k], dot);
        zsq = fmaf(zk, zk, zsq);
    }
    float logit = -0.5f * (zsq + g_csq[t] - 2.f * dot);
    float bm = block_reduce(logit, red, 1);
    float e  = expf(logit - bm);
    float bs = block_reduce(e, red, 0);
    float p  = e / bs;
    ophi[(size_t)n * TD + t] = p;
    g_phi[n * TD + t] = __float2half_rn(p * PHI_SC);
}
__global__ void k_softmax_V() {
    int row = blockIdx.x;
    float* X = g_beta + (size_t)row * VD;
    __shared__ float red[33];
    int t = threadIdx.x;
    float s = 0.f;
    for (int i = t; i < VD; i += blockDim.x) { float e = expf(X[i]); X[i] = e; s += e; }
    float bs = block_reduce(s, red, 0);
    if (t == 0) g_sinv[row] = 1.f / bs;
}
__global__ void k_transpose() {
    __shared__ float tile[32][33];
    int v0 = blockIdx.x * 32, t0 = blockIdx.y * 32;
    int tx = threadIdx.x, ty = threadIdx.y;
    #pragma unroll
    for (int i = 0; i < 4; i++) {
        int vc = v0 + tx;
        tile[ty + i * 8][tx] = (vc < VD) ? g_beta[(size_t)(t0 + ty + i * 8) * VD + vc] : 0.f;
    }
    __syncthreads();
    float sc = g_sinv[t0 + tx] * BETA_SC;
    #pragma unroll
    for (int i = 0; i < 4; i++) {
        int vr = v0 + ty + i * 8, tc = t0 + tx;
        if (vr < VD) g_btT[(size_t)vr * TD + tc] = __float2half_rn(tile[tx][ty + i * 8] * sc);
    }
}

// ---------------- launch ----------------
extern "C" void kernel_launch(void* const* d_in, const int* in_sizes, int n_in,
                              void* d_out, int out_size) {
    const float* input_  = (const float*)d_in[0];
    const float* eps     = (const float*)d_in[2];
    const float* W1      = (const float*)d_in[3];
    const float* b1      = (const float*)d_in[4];
    const float* W2      = (const float*)d_in[5];
    const float* b2      = (const float*)d_in[6];
    const float* Wm      = (const float*)d_in[7];
    const float* bm      = (const float*)d_in[8];
    const float* Wv      = (const float*)d_in[9];
    const float* bv      = (const float*)d_in[10];
    const float* gm      = (const float*)d_in[11];
    const float* betam   = (const float*)d_in[12];
    const float* gv      = (const float*)d_in[13];
    const float* betav   = (const float*)d_in[14];
    const float* centres = (const float*)d_in[15];
    const float* mu_z    = (const float*)d_in[16];
    const float* emb     = (const float*)d_in[17];

    float* out       = (float*)d_out;
    float* out_z     = out + OFF_Z;
    float* out_recon = out + OFF_RECON;
    float* out_zx    = out + OFF_ZX;
    float* out_zc    = out + OFF_ZC;
    float* out_phi   = out + OFF_PHI;

    #define GSA(p, s) void* p; cudaGetSymbolAddress(&p, s)
    GSA(p_in_hi, g_in_hi);   GSA(p_in_lo, g_in_lo);
    GSA(p_w1_hi, g_w1_hi);   GSA(p_w1_lo, g_w1_lo);
    GSA(p_w2_hi, g_w2_hi);   GSA(p_w2_lo, g_w2_lo);
    GSA(p_wmv_hi, g_wmv_hi); GSA(p_wmv_lo, g_wmv_lo);
    GSA(p_part, g_part);
    GSA(p_en1_hi, g_en1_hi); GSA(p_en1_lo, g_en1_lo);
    GSA(p_en2_hi, g_en2_hi); GSA(p_en2_lo, g_en2_lo);
    GSA(p_phi, g_phi);       GSA(p_muz, g_muz);
    GSA(p_emb, g_emb);       GSA(p_beta, g_beta);
    GSA(p_btT, g_btT);

    static cudaStream_t s2 = nullptr;
    static cudaEvent_t e0 = nullptr, eW = nullptr, eB = nullptr;
    if (!s2) {
        cudaStreamCreateWithFlags(&s2, cudaStreamNonBlocking);
        cudaEventCreateWithFlags(&e0, cudaEventDisableTiming);
        cudaEventCreateWithFlags(&eW, cudaEventDisableTiming);
        cudaEventCreateWithFlags(&eB, cudaEventDisableTiming);
    }

    const int SM_SPLIT  = 2 * (2 * 16384 + 2 * 32768);   // 196608, 2 stages
    const int SM_SINGLE = 3 * (16384 + 32768);           // 147456, 3 stages
    // set max-dynamic-smem on EVERY instantiated variant (R13 failure: pmv's
    // NPRED=true split variant was missing -> launch error poisoned capture)
    cudaFuncSetAttribute((const void*)gemm_mma<true, 0, false, 0, false, 2>,
                         cudaFuncAttributeMaxDynamicSharedMemorySize, SM_SPLIT);
    cudaFuncSetAttribute((const void*)gemm_mma<true, 0, false, 0, true, 2>,
                         cudaFuncAttributeMaxDynamicSharedMemorySize, SM_SPLIT);
    cudaFuncSetAttribute((const void*)gemm_mma<true, 1, true, 1, false, 2>,
                         cudaFuncAttributeMaxDynamicSharedMemorySize, SM_SPLIT);
    cudaFuncSetAttribute((const void*)gemm_mma<false, 0, false, 0, true, 3>,
                         cudaFuncAttributeMaxDynamicSharedMemorySize, SM_SINGLE);

    // ---- critical path: GEMM1 prerequisites ----
    k_split_pad4<<<1024, 256>>>(input_, (__half*)p_in_hi, (__half*)p_in_lo, NB, VD, VDP);
    k_split_pad4<<<1024, 256>>>(W1, (__half*)p_w1_hi, (__half*)p_w1_lo, E1D, VD, VDP);

    // fork side stream
    cudaEventRecord(e0, 0);
    cudaStreamWaitEvent(s2, e0, 0);
    k_split_pad4<<<512, 256, 0, s2>>>(W2, (__half*)p_w2_hi, (__half*)p_w2_lo, E2D, E1D, E1D);

    // GEMM1: input @ W1^T (3-split, split-K=2) -> 128 CTAs = 1 wave
    gemm_mma<true, 0, false, 0, false, 2><<<dim3(E1D / 256, NB / 128, 2), 256, SM_SPLIT>>>(
        (const __half*)p_in_hi, (const __half*)p_in_lo,
        (const __half*)p_w1_hi, (const __half*)p_w1_lo,
        E1D, VDP, VDP, E1D, VDP / 64, nullptr, (float*)p_part, nullptr, nullptr,
        (size_t)NB * E1D, 1.f);

    // side stream: GEMM2/pmv weights + centres, then beta chain
    k_pack_wmv<<<(CD * E2D + 255) / 256, 256, 0, s2>>>(Wm, bm, Wv, bv);
    k_centres<<<TD, 32, 0, s2>>>(centres, out_zc);
    cudaEventRecord(eW, s2);
    k_conv_pad4<<<128, 256, 0, s2>>>(mu_z, (__half*)p_muz, TD, EMBD, EMBP, 1.f);
    k_conv_pad4<<<512, 256, 0, s2>>>(emb, (__half*)p_emb, VD, EMBD, EMBP, 1.f);
    gemm_mma<false, 0, false, 0, true, 3><<<dim3(VDP / 256, TD / 128, 1), 256, SM_SINGLE, s2>>>(
        (const __half*)p_muz, nullptr, (const __half*)p_emb, nullptr,
        VD, EMBP, EMBP, VD, EMBP / 64, nullptr, (float*)p_beta, nullptr, nullptr, 0, 1.f);
    k_softmax_V<<<TD, 512, 0, s2>>>();
    k_transpose<<<dim3((VD + 31) / 32, TD / 32), dim3(32, 8), 0, s2>>>();
    cudaEventRecord(eB, s2);

    // main stream continues
    k_reduce_en1<<<(NB * E1D + 255) / 256, 256>>>(b1);

    cudaStreamWaitEvent(0, eW, 0);
    gemm_mma<true, 1, true, 1, false, 2><<<dim3(E2D / 256, NB / 128, 1), 256, SM_SPLIT>>>(
        (const __half*)p_en1_hi, (const __half*)p_en1_lo,
        (const __half*)p_w2_hi, (const __half*)p_w2_lo,
        E2D, E1D, E1D, E2D, E1D / 64, b2, nullptr,
        (__half*)p_en2_hi, (__half*)p_en2_lo, 0, 1.f);

    // pmv: N=128 (B zero-padded to 256 rows), split-K=4
    gemm_mma<true, 0, false, 0, true, 2><<<dim3(1, NB / 128, 4), 256, SM_SPLIT>>>(
        (const __half*)p_en2_hi, (const __half*)p_en2_lo,
        (const __half*)p_wmv_hi, (const __half*)p_wmv_lo,
        2 * CD, E2D, E2D, 2 * CD, E2D / 64, nullptr, (float*)p_part, nullptr, nullptr,
        (size_t)NB * 2 * CD, 1.f);
    k_pmv_reduce<<<(NB * 2 * CD + 255) / 256, 256>>>();

    k_bn_stats<<<2 * CD, 256>>>();
    k_z<<<(NB * CD + 255) / 256, 256>>>(eps, gm, betam, gv, betav, out_z, out_zx);
    k_rbf<<<NB, TD>>>(centres, out_phi);

    cudaStreamWaitEvent(0, eB, 0);
    gemm_mma<false, 0, false, 0, true, 3><<<dim3(VDP / 256, NB / 128, 1), 256, SM_SINGLE>>>(
        (const __half*)p_phi, nullptr, (const __half*)p_btT, nullptr,
        VD, TD, TD, VD, TD / 64, nullptr, out_recon, nullptr, nullptr, 0,
        1.f / (PHI_SC * BETA_SC));
}

// round 17
// speedup vs baseline: 2.3712x; 1.5418x over previous
#include <cuda_runtime.h>
#include <cuda_fp16.h>
#include <math.h>
#include <stdint.h>

#define NB   2048
#define VD   30000
#define VDP  30208            // mult of 256
#define E1D  1024
#define E2D  1024
#define CD   64
#define TD   512
#define EMBD 300
#define EMBP 320
#define BN_EPS 1e-5f

#define PHI_SC  256.f
#define BETA_SC 1024.f

#define OFF_Z      0
#define OFF_RECON  (NB*CD)
#define OFF_ZX     (OFF_RECON + (size_t)NB*VD)
#define OFF_ZC     (OFF_ZX + NB*CD)
#define OFF_PHI    (OFF_ZC + TD*CD)

// ---------------- scratch ----------------
__device__ __align__(1024) __half g_in_hi [(size_t)NB * VDP];
__device__ __align__(1024) __half g_w1_hi [(size_t)E1D * VDP];
__device__ __align__(1024) __half g_w2_hi [E2D * E1D];
__device__ __align__(1024) __half g_w2_lo [E2D * E1D];
__device__ __align__(1024) __half g_wmv_hi[256 * E2D];   // rows 128..255 stay zero
__device__ __align__(1024) __half g_wmv_lo[256 * E2D];
__device__ float g_bmv[2 * CD];
__device__ __align__(1024) __half g_en1_hi[NB * E1D];
__device__ __align__(1024) __half g_en1_lo[NB * E1D];
__device__ __align__(1024) __half g_en2_hi[NB * E2D];
__device__ __align__(1024) __half g_en2_lo[NB * E2D];
__device__ __align__(1024) float g_part[4 * NB * 2 * CD > 2 * NB * E1D ? 4 * NB * 2 * CD : 2 * NB * E1D];
__device__ float g_pmv [NB * 2 * CD];
__device__ float g_stats[4 * CD];
__device__ float g_z[NB * CD];
__device__ float g_csq[TD];
__device__ float g_sinv[TD];
__device__ __align__(1024) __half g_phi [NB * TD];
__device__ __align__(1024) __half g_muz [TD * EMBP];
__device__ __align__(1024) __half g_emb [(size_t)VDP * EMBP];
__device__ float g_beta[(size_t)TD * VD];
__device__ __align__(1024) __half g_btT [(size_t)VDP * TD];

// ---------------- helpers ----------------
__device__ __forceinline__ uint32_t smem_to_u32(const void* p) {
    uint32_t a;
    asm("{ .reg .u64 t; cvta.to.shared.u64 t, %1; cvt.u32.u64 %0, t; }" : "=r"(a) : "l"(p));
    return a;
}
#define SWZ(x) ((uint32_t)(x) ^ ((((uint32_t)(x)) >> 3) & 0x70))

#define LDSM4(r, addr) \
    asm volatile("ldmatrix.sync.aligned.m8n8.x4.shared.b16 {%0,%1,%2,%3}, [%4];" \
        : "=r"((r)[0]), "=r"((r)[1]), "=r"((r)[2]), "=r"((r)[3]) : "r"(addr))

#define MMA16816(d, a, b0, b1) \
    asm volatile("mma.sync.aligned.m16n8k16.row.col.f32.f16.f16.f32 " \
        "{%0,%1,%2,%3}, {%4,%5,%6,%7}, {%8,%9}, {%0,%1,%2,%3};" \
        : "+f"((d)[0]), "+f"((d)[1]), "+f"((d)[2]), "+f"((d)[3]) \
        : "r"((a)[0]), "r"((a)[1]), "r"((a)[2]), "r"((a)[3]), "r"(b0), "r"(b1))

__device__ __forceinline__ float softplusf(float x) {
    return fmaxf(x, 0.f) + log1pf(expf(-fabsf(x)));
}
__device__ __forceinline__ void split2(float x, __half& h, __half& l) {
    h = __float2half_rn(x);
    l = __float2half_rn(x - __half2float(h));
}
__device__ __forceinline__ float block_reduce(float v, float* red, int op) {
    int t = threadIdx.x, w = t >> 5, l = t & 31, nw = blockDim.x >> 5;
    #pragma unroll
    for (int o = 16; o > 0; o >>= 1) {
        float u = __shfl_xor_sync(0xffffffffu, v, o);
        v = op ? fmaxf(v, u) : (v + u);
    }
    if (l == 0) red[w] = v;
    __syncthreads();
    if (t == 0) {
        float r = red[0];
        for (int i = 1; i < nw; i++) r = op ? fmaxf(r, red[i]) : (r + red[i]);
        red[32] = r;
    }
    __syncthreads();
    float r = red[32];
    __syncthreads();
    return r;
}

// ---------------- fp16 mma.sync GEMM ----------------
// CTA tile 128(M) x 256(N) x 64(K). 256 threads = 8 warps as 2(M) x 4(N),
// warp tile 64x64.
template<bool SPLIT, int OUTM, bool HAS_BIAS, int ACT, bool NPRED, int STAGES>
__global__ void __launch_bounds__(256, 1)
gemm_mma(const __half* __restrict__ Ah, const __half* __restrict__ Al,
         const __half* __restrict__ Bh, const __half* __restrict__ Bl,
         int Nn, int ldA, int ldB, int ldC, int kChunks,
         const float* __restrict__ bias, float* __restrict__ C,
         __half* __restrict__ Chi, __half* __restrict__ Clo, size_t zStride, float outScale)
{
    constexpr int TA  = 128 * 128;               // A tile bytes
    constexpr int TBB = 256 * 128;               // B tile bytes
    constexpr int STG = (SPLIT ? 2 * TA + 2 * TBB : TA + TBB);
    extern __shared__ char smem[];
    const uint32_t sb = smem_to_u32(smem);
    const int tid = threadIdx.x, lane = tid & 31, wid = tid >> 5;
    const int wM = wid & 1, wN = wid >> 1;       // 2(M) x 4(N)
    const int m0 = blockIdx.y * 128, n0 = blockIdx.x * 256;
    const int per = kChunks / gridDim.z, cbeg = blockIdx.z * per;

    float acc[4][8][4];
    #pragma unroll
    for (int a = 0; a < 4; a++)
        #pragma unroll
        for (int b = 0; b < 8; b++)
            #pragma unroll
            for (int c = 0; c < 4; c++) acc[a][b][c] = 0.f;

    auto load_stage = [&](int s, int c) {
        const int k0 = c * 64;
        const uint32_t st = sb + s * STG;
        #pragma unroll
        for (int t = 0; t < (SPLIT ? 2 : 1); t++) {
            const __half* base = t ? Al : Ah;
            #pragma unroll
            for (int i = 0; i < 4; i++) {
                int lin = tid + i * 256, row = lin >> 3, kc = lin & 7;
                const __half* src = base + (size_t)(m0 + row) * ldA + k0 + kc * 8;
                uint32_t dst = st + t * TA + SWZ(row * 128 + kc * 16);
                asm volatile("cp.async.cg.shared.global [%0], [%1], 16;" :: "r"(dst), "l"(src));
            }
        }
        const uint32_t bo = st + (SPLIT ? 2 : 1) * TA;
        #pragma unroll
        for (int t = 0; t < (SPLIT ? 2 : 1); t++) {
            const __half* base = t ? Bl : Bh;
            #pragma unroll
            for (int i = 0; i < 8; i++) {
                int lin = tid + i * 256, row = lin >> 3, kc = lin & 7;
                const __half* src = base + (size_t)(n0 + row) * ldB + k0 + kc * 8;
                uint32_t dst = bo + t * TBB + SWZ(row * 128 + kc * 16);
                asm volatile("cp.async.cg.shared.global [%0], [%1], 16;" :: "r"(dst), "l"(src));
            }
        }
        asm volatile("cp.async.commit_group;" ::: "memory");
    };

    auto compute_stage = [&](int s) {
        const uint32_t st = sb + s * STG;
        const uint32_t aH = st, aL = st + TA;
        const uint32_t bH = st + (SPLIT ? 2 : 1) * TA, bL = bH + TBB;
        #pragma unroll
        for (int ks = 0; ks < 4; ks++) {
            uint32_t rah[4][4], ral[4][4];
            #pragma unroll
            for (int mt = 0; mt < 4; mt++) {
                int row = wM * 64 + mt * 16 + (lane & 15);
                int kb  = ks * 32 + ((lane >> 4) << 4);
                uint32_t off = SWZ(row * 128 + kb);
                LDSM4(rah[mt], aH + off);
                if (SPLIT) LDSM4(ral[mt], aL + off);
            }
            #pragma unroll
            for (int p = 0; p < 4; p++) {
                uint32_t rbh[4], rbl[4];
                {
                    int nr = wN * 64 + p * 16 + (lane & 7) + ((lane >> 4) << 3);
                    int kb = ks * 32 + (((lane >> 3) & 1) << 4);
                    uint32_t off = SWZ(nr * 128 + kb);
                    LDSM4(rbh, bH + off);
                    if (SPLIT) LDSM4(rbl, bL + off);
                }
                #pragma unroll
                for (int mt = 0; mt < 4; mt++) {
                    MMA16816(acc[mt][p * 2 + 0], rah[mt], rbh[0], rbh[1]);
                    MMA16816(acc[mt][p * 2 + 1], rah[mt], rbh[2], rbh[3]);
                }
                if (SPLIT) {
                    #pragma unroll
                    for (int mt = 0; mt < 4; mt++) {
                        MMA16816(acc[mt][p * 2 + 0], rah[mt], rbl[0], rbl[1]);
                        MMA16816(acc[mt][p * 2 + 1], rah[mt], rbl[2], rbl[3]);
                    }
                    #pragma unroll
                    for (int mt = 0; mt < 4; mt++) {
                        MMA16816(acc[mt][p * 2 + 0], ral[mt], rbh[0], rbh[1]);
                        MMA16816(acc[mt][p * 2 + 1], ral[mt], rbh[2], rbh[3]);
                    }
                }
            }
        }
    };

    #pragma unroll
    for (int s = 0; s < STAGES - 1; s++) load_stage(s, cbeg + s);
    for (int c = 0; c < per; c++) {
        if (c + STAGES - 1 < per) load_stage((c + STAGES - 1) % STAGES, cbeg + c + STAGES - 1);
        else asm volatile("cp.async.commit_group;" ::: "memory");
        asm volatile("cp.async.wait_group %0;" :: "n"(STAGES - 1));
        __syncthreads();
        compute_stage(c % STAGES);
        __syncthreads();
    }

    float* Cz = C;
    if (OUTM == 0) Cz = C + (size_t)blockIdx.z * zStride;
    #pragma unroll
    for (int mt = 0; mt < 4; mt++) {
        #pragma unroll
        for (int nt = 0; nt < 8; nt++) {
            int row = m0 + wM * 64 + mt * 16 + (lane >> 2);
            int col = n0 + wN * 64 + nt * 8 + ((lane & 3) << 1);
            if (NPRED && col >= Nn) continue;
            #pragma unroll
            for (int h = 0; h < 2; h++) {
                int r = row + h * 8;
                float v0 = acc[mt][nt][h * 2 + 0], v1 = acc[mt][nt][h * 2 + 1];
                if (OUTM == 0) { v0 *= outScale; v1 *= outScale; }
                if (HAS_BIAS) { v0 += bias[col]; v1 += bias[col + 1]; }
                if (ACT == 1) { v0 = softplusf(v0); v1 = softplusf(v1); }
                if (OUTM == 0) {
                    float2 f; f.x = v0; f.y = v1;
                    *reinterpret_cast<float2*>(Cz + (size_t)r * ldC + col) = f;
                } else {
                    __half h0, l0, h1, l1;
                    split2(v0, h0, l0); split2(v1, h1, l1);
                    __half2 ph; ph.x = h0; ph.y = h1;
                    __half2 pl; pl.x = l0; pl.y = l1;
                    *reinterpret_cast<__half2*>(Chi + (size_t)r * ldC + col) = ph;
                    *reinterpret_cast<__half2*>(Clo + (size_t)r * ldC + col) = pl;
                }
            }
        }
    }
}

// ---------------- conversion kernels ----------------
struct H4 { __half2 a, b; };
__device__ __forceinline__ void store_h4(__half* p, __half2 x, __half2 y) {
    H4 v; v.a = x; v.b = y;
    *reinterpret_cast<H4*>(p) = v;
}
__global__ void k_split_pad4(const float* __restrict__ s, __half* __restrict__ h,
                             __half* __restrict__ l, int rows, int sc, int dc) {
    size_t n4 = (size_t)rows * dc / 4;
    size_t i = (size_t)blockIdx.x * blockDim.x + threadIdx.x, st = (size_t)gridDim.x * blockDim.x;
    for (; i < n4; i += st) {
        size_t e = i * 4;
        int r = (int)(e / dc), c = (int)(e % dc);
        float4 v = make_float4(0.f, 0.f, 0.f, 0.f);
        if (c < sc) v = *reinterpret_cast<const float4*>(s + (size_t)r * sc + c);
        __half h0, l0, h1, l1, h2, l2, h3, l3;
        split2(v.x, h0, l0); split2(v.y, h1, l1); split2(v.z, h2, l2); split2(v.w, h3, l3);
        __half2 ph0; ph0.x = h0; ph0.y = h1;  __half2 ph1; ph1.x = h2; ph1.y = h3;
        __half2 pl0; pl0.x = l0; pl0.y = l1;  __half2 pl1; pl1.x = l2; pl1.y = l3;
        store_h4(h + e, ph0, ph1);
        store_h4(l + e, pl0, pl1);
    }
}
__global__ void k_conv_pad4(const float* __restrict__ s, __half* __restrict__ d,
                            int rows, int sc, int dc, float sc_mul) {
    size_t n4 = (size_t)rows * dc / 4;
    size_t i = (size_t)blockIdx.x * blockDim.x + threadIdx.x, st = (size_t)gridDim.x * blockDim.x;
    for (; i < n4; i += st) {
        size_t e = i * 4;
        int r = (int)(e / dc), c = (int)(e % dc);
        float4 v = make_float4(0.f, 0.f, 0.f, 0.f);
        if (c < sc) v = *reinterpret_cast<const float4*>(s + (size_t)r * sc + c);
        __half2 p0 = __floats2half2_rn(v.x * sc_mul, v.y * sc_mul);
        __half2 p1 = __floats2half2_rn(v.z * sc_mul, v.w * sc_mul);
        store_h4(d + e, p0, p1);
    }
}
__global__ void k_pack_wmv(const float* __restrict__ Wm, const float* __restrict__ bm,
                           const float* __restrict__ Wv, const float* __restrict__ bv) {
    int i = blockIdx.x * blockDim.x + threadIdx.x;
    const int tot = CD * E2D;
    if (i < tot) {
        __half h, l;
        split2(Wm[i], h, l); g_wmv_hi[i] = h;       g_wmv_lo[i] = l;
        split2(Wv[i], h, l); g_wmv_hi[tot + i] = h; g_wmv_lo[tot + i] = l;
    }
    if (i < CD) { g_bmv[i] = bm[i]; g_bmv[CD + i] = bv[i]; }
}
__global__ void k_reduce_en1(const float* __restrict__ b1) {
    int i = blockIdx.x * blockDim.x + threadIdx.x;
    if (i >= NB * E1D) return;
    float v = softplusf(g_part[i] + g_part[NB * E1D + i] + b1[i & (E1D - 1)]);
    __half h, l; split2(v, h, l);
    g_en1_hi[i] = h; g_en1_lo[i] = l;
}
__global__ void k_pmv_reduce() {
    int i = blockIdx.x * blockDim.x + threadIdx.x;
    if (i >= NB * 2 * CD) return;
    float v = g_bmv[i & (2 * CD - 1)];
    #pragma unroll
    for (int z = 0; z < 4; z++) v += g_part[(size_t)z * NB * 2 * CD + i];
    g_pmv[i] = v;
}
__global__ void k_bn_stats() {
    int c = blockIdx.x;
    float s = 0.f, s2 = 0.f;
    for (int n = threadIdx.x; n < NB; n += blockDim.x) {
        float x = g_pmv[n * (2 * CD) + c];
        s += x; s2 += x * x;
    }
    __shared__ float red[33];
    float S = block_reduce(s, red, 0), S2 = block_reduce(s2, red, 0);
    if (threadIdx.x == 0) {
        float mean = S * (1.f / NB);
        float var  = S2 * (1.f / NB) - mean * mean;
        g_stats[c] = mean;
        g_stats[2 * CD + c] = rsqrtf(var + BN_EPS);
    }
}
__global__ void k_z(const float* __restrict__ eps, const float* __restrict__ gm,
                    const float* __restrict__ betam, const float* __restrict__ gv,
                    const float* __restrict__ betav, float* __restrict__ oz, float* __restrict__ ozx) {
    int i = blockIdx.x * blockDim.x + threadIdx.x;
    if (i >= NB * CD) return;
    int n = i / CD, c = i % CD;
    float pm = g_pmv[n * (2 * CD) + c], pv = g_pmv[n * (2 * CD) + CD + c];
    float pmean   = (pm - g_stats[c])      * g_stats[2 * CD + c] * gm[c] + betam[c];
    float plogvar = (pv - g_stats[CD + c]) * g_stats[3 * CD + c] * gv[c] + betav[c];
    float z = pmean + expf(0.5f * plogvar) * eps[i];
    g_z[i] = z; oz[i] = z; ozx[i] = z;
}
__global__ void k_centres(const float* __restrict__ cen, float* __restrict__ ozc) {
    int t = blockIdx.x, l = threadIdx.x;
    float a = cen[t * CD + l], b = cen[t * CD + 32 + l];
    ozc[t * CD + l] = a; ozc[t * CD + 32 + l] = b;
    float s = a * a + b * b;
    #pragma unroll
    for (int o = 16; o > 0; o >>= 1) s += __shfl_xor_sync(0xffffffffu, s, o);
    if (l == 0) g_csq[t] = s;
}
__global__ void k_rbf(const float* __restrict__ cen, float* __restrict__ ophi) {
    int n = blockIdx.x, t = threadIdx.x;
    __shared__ float zsh[CD];
    __shared__ float red[33];
    if (t < CD) zsh[t] = g_z[n * CD + t];
    __syncthreads();
    float dot = 0.f, zsq = 0.f;
    const float* cp = cen + t * CD;
    #pragma unroll
    for (int k = 0; k < CD; k++) {
        float zk = zsh[k];
        dot = fmaf(zk, cp[k], dot);
        zsq = fmaf(zk, zk, zsq);
    }
    float logit = -0.5f * (zsq + g_csq[t] - 2.f * dot);
    float bm = block_reduce(logit, red, 1);
    float e  = expf(logit - bm);
    float bs = block_reduce(e, red, 0);
    float p  = e / bs;
    ophi[(size_t)n * TD + t] = p;
    g_phi[n * TD + t] = __float2half_rn(p * PHI_SC);
}
__global__ void k_softmax_V() {
    int row = blockIdx.x;
    float* X = g_beta + (size_t)row * VD;
    __shared__ float red[33];
    int t = threadIdx.x;
    float s = 0.f;
    for (int i = t; i < VD; i += blockDim.x) { float e = expf(X[i]); X[i] = e; s += e; }
    float bs = block_reduce(s, red, 0);
    if (t == 0) g_sinv[row] = 1.f / bs;
}
__global__ void k_transpose() {
    __shared__ float tile[32][33];
    int v0 = blockIdx.x * 32, t0 = blockIdx.y * 32;
    int tx = threadIdx.x, ty = threadIdx.y;
    #pragma unroll
    for (int i = 0; i < 4; i++) {
        int vc = v0 + tx;
        tile[ty + i * 8][tx] = (vc < VD) ? g_beta[(size_t)(t0 + ty + i * 8) * VD + vc] : 0.f;
    }
    __syncthreads();
    float sc = g_sinv[t0 + tx] * BETA_SC;
    #pragma unroll
    for (int i = 0; i < 4; i++) {
        int vr = v0 + ty + i * 8, tc = t0 + tx;
        if (vr < VD) g_btT[(size_t)vr * TD + tc] = __float2half_rn(tile[tx][ty + i * 8] * sc);
    }
}

// ---------------- launch ----------------
extern "C" void kernel_launch(void* const* d_in, const int* in_sizes, int n_in,
                              void* d_out, int out_size) {
    const float* input_  = (const float*)d_in[0];
    const float* eps     = (const float*)d_in[2];
    const float* W1      = (const float*)d_in[3];
    const float* b1      = (const float*)d_in[4];
    const float* W2      = (const float*)d_in[5];
    const float* b2      = (const float*)d_in[6];
    const float* Wm      = (const float*)d_in[7];
    const float* bm      = (const float*)d_in[8];
    const float* Wv      = (const float*)d_in[9];
    const float* bv      = (const float*)d_in[10];
    const float* gm      = (const float*)d_in[11];
    const float* betam   = (const float*)d_in[12];
    const float* gv      = (const float*)d_in[13];
    const float* betav   = (const float*)d_in[14];
    const float* centres = (const float*)d_in[15];
    const float* mu_z    = (const float*)d_in[16];
    const float* emb     = (const float*)d_in[17];

    float* out       = (float*)d_out;
    float* out_z     = out + OFF_Z;
    float* out_recon = out + OFF_RECON;
    float* out_zx    = out + OFF_ZX;
    float* out_zc    = out + OFF_ZC;
    float* out_phi   = out + OFF_PHI;

    #define GSA(p, s) void* p; cudaGetSymbolAddress(&p, s)
    GSA(p_in_hi, g_in_hi);
    GSA(p_w1_hi, g_w1_hi);
    GSA(p_w2_hi, g_w2_hi);   GSA(p_w2_lo, g_w2_lo);
    GSA(p_wmv_hi, g_wmv_hi); GSA(p_wmv_lo, g_wmv_lo);
    GSA(p_part, g_part);
    GSA(p_en1_hi, g_en1_hi); GSA(p_en1_lo, g_en1_lo);
    GSA(p_en2_hi, g_en2_hi); GSA(p_en2_lo, g_en2_lo);
    GSA(p_phi, g_phi);       GSA(p_muz, g_muz);
    GSA(p_emb, g_emb);       GSA(p_beta, g_beta);
    GSA(p_btT, g_btT);

    static cudaStream_t s2 = nullptr;
    static cudaEvent_t e0 = nullptr, eW = nullptr, eB = nullptr;
    if (!s2) {
        cudaStreamCreateWithFlags(&s2, cudaStreamNonBlocking);
        cudaEventCreateWithFlags(&e0, cudaEventDisableTiming);
        cudaEventCreateWithFlags(&eW, cudaEventDisableTiming);
        cudaEventCreateWithFlags(&eB, cudaEventDisableTiming);
    }

    const int SM_SPLIT  = 2 * (2 * 16384 + 2 * 32768);   // 196608, 2 stages
    const int SM_SINGLE = 3 * (16384 + 32768);           // 147456, 3 stages
    // attributes for EVERY instantiated variant
    cudaFuncSetAttribute((const void*)gemm_mma<false, 0, false, 0, false, 3>,
                         cudaFuncAttributeMaxDynamicSharedMemorySize, SM_SINGLE);
    cudaFuncSetAttribute((const void*)gemm_mma<false, 0, false, 0, true, 3>,
                         cudaFuncAttributeMaxDynamicSharedMemorySize, SM_SINGLE);
    cudaFuncSetAttribute((const void*)gemm_mma<true, 0, false, 0, true, 2>,
                         cudaFuncAttributeMaxDynamicSharedMemorySize, SM_SPLIT);
    cudaFuncSetAttribute((const void*)gemm_mma<true, 1, true, 1, false, 2>,
                         cudaFuncAttributeMaxDynamicSharedMemorySize, SM_SPLIT);

    // ---- critical path: GEMM1 prerequisites (single fp16 now) ----
    k_conv_pad4<<<1024, 256>>>(input_, (__half*)p_in_hi, NB, VD, VDP, 1.f);
    k_conv_pad4<<<1024, 256>>>(W1, (__half*)p_w1_hi, E1D, VD, VDP, 1.f);

    // fork side stream
    cudaEventRecord(e0, 0);
    cudaStreamWaitEvent(s2, e0, 0);
    k_split_pad4<<<512, 256, 0, s2>>>(W2, (__half*)p_w2_hi, (__half*)p_w2_lo, E2D, E1D, E1D);

    // GEMM1: input @ W1^T (SINGLE fp16 pass, split-K=2 -> 128 CTAs)
    gemm_mma<false, 0, false, 0, false, 3><<<dim3(E1D / 256, NB / 128, 2), 256, SM_SINGLE>>>(
        (const __half*)p_in_hi, nullptr,
        (const __half*)p_w1_hi, nullptr,
        E1D, VDP, VDP, E1D, VDP / 64, nullptr, (float*)p_part, nullptr, nullptr,
        (size_t)NB * E1D, 1.f);

    // side stream: GEMM2/pmv weights + centres, then beta chain
    k_pack_wmv<<<(CD * E2D + 255) / 256, 256, 0, s2>>>(Wm, bm, Wv, bv);
    k_centres<<<TD, 32, 0, s2>>>(centres, out_zc);
    cudaEventRecord(eW, s2);
    k_conv_pad4<<<128, 256, 0, s2>>>(mu_z, (__half*)p_muz, TD, EMBD, EMBP, 1.f);
    k_conv_pad4<<<512, 256, 0, s2>>>(emb, (__half*)p_emb, VD, EMBD, EMBP, 1.f);
    gemm_mma<false, 0, false, 0, true, 3><<<dim3(VDP / 256, TD / 128, 1), 256, SM_SINGLE, s2>>>(
        (const __half*)p_muz, nullptr, (const __half*)p_emb, nullptr,
        VD, EMBP, EMBP, VD, EMBP / 64, nullptr, (float*)p_beta, nullptr, nullptr, 0, 1.f);
    k_softmax_V<<<TD, 512, 0, s2>>>();
    k_transpose<<<dim3((VD + 31) / 32, TD / 32), dim3(32, 8), 0, s2>>>();
    cudaEventRecord(eB, s2);

    // main stream continues
    k_reduce_en1<<<(NB * E1D + 255) / 256, 256>>>(b1);

    cudaStreamWaitEvent(0, eW, 0);
    gemm_mma<true, 1, true, 1, false, 2><<<dim3(E2D / 256, NB / 128, 1), 256, SM_SPLIT>>>(
        (const __half*)p_en1_hi, (const __half*)p_en1_lo,
        (const __half*)p_w2_hi, (const __half*)p_w2_lo,
        E2D, E1D, E1D, E2D, E1D / 64, b2, nullptr,
        (__half*)p_en2_hi, (__half*)p_en2_lo, 0, 1.f);

    // pmv: N=128 (B zero-padded to 256 rows), split-K=4, 3-split
    gemm_mma<true, 0, false, 0, true, 2><<<dim3(1, NB / 128, 4), 256, SM_SPLIT>>>(
        (const __half*)p_en2_hi, (const __half*)p_en2_lo,
        (const __half*)p_wmv_hi, (const __half*)p_wmv_lo,
        2 * CD, E2D, E2D, 2 * CD, E2D / 64, nullptr, (float*)p_part, nullptr, nullptr,
        (size_t)NB * 2 * CD, 1.f);
    k_pmv_reduce<<<(NB * 2 * CD + 255) / 256, 256>>>();

    k_bn_stats<<<2 * CD, 256>>>();
    k_z<<<(NB * CD + 255) / 256, 256>>>(eps, gm, betam, gv, betav, out_z, out_zx);
    k_rbf<<<NB, TD>>>(centres, out_phi);

    cudaStreamWaitEvent(0, eB, 0);
    gemm_mma<false, 0, false, 0, true, 3><<<dim3(VDP / 256, NB / 128, 1), 256, SM_SINGLE>>>(
        (const __half*)p_phi, nullptr, (const __half*)p_btT, nullptr,
        VD, TD, TD, VD, TD / 64, nullptr, out_recon, nullptr, nullptr, 0,
        1.f / (PHI_SC * BETA_SC));
}